// round 1
// baseline (speedup 1.0000x reference)
#include <cuda_runtime.h>
#include <math.h>
#include <stdint.h>

// ---------------------------------------------------------------------------
// Problem dims (fixed by the reference): F = 8192 frames, feature chain
//   X[2049,F] -> E1[1000,F] -> E[400,F] -> Gx[800,F] -> scan H[200,F]
//   Cat = [H;E][600,F] -> T1[800,F] -> T2[400,F] -> D[1000,F] -> out[2049,F]
// ---------------------------------------------------------------------------
#define FMAX 8192

__device__ float g_E1 [1000 * FMAX];
__device__ float g_Cat[ 600 * FMAX];   // rows 0..200 = H (scan), rows 200..600 = E
__device__ float g_Gx [ 800 * FMAX];
__device__ float g_T1 [ 800 * FMAX];
__device__ float g_T2 [ 400 * FMAX];
__device__ float g_D  [1000 * FMAX];
__device__ float g_bsum[800];

__device__ __forceinline__ float sigf(float x) { return 1.0f / (1.0f + expf(-x)); }

// packed f32x2 helpers (ptxas won't auto-fuse; PTX-only path)
__device__ __forceinline__ void fma2(unsigned long long& acc,
                                     unsigned long long a, unsigned long long b) {
    asm("fma.rn.f32x2 %0, %1, %2, %0;" : "+l"(acc) : "l"(a), "l"(b));
}
__device__ __forceinline__ unsigned long long pack2(float x, float y) {
    unsigned long long v;
    asm("mov.b64 %0, {%1, %2};" : "=l"(v) : "f"(x), "f"(y));
    return v;
}
__device__ __forceinline__ void unpack2(float& lo, float& hi, unsigned long long v) {
    asm("mov.b64 {%0, %1}, %2;" : "=f"(lo), "=f"(hi) : "l"(v));
}

// ---------------------------------------------------------------------------
// GEMM: C[M,N] = act(A[M,K] @ B[K,N] + bias[M]); ACT: 0=lrelu, 1=none,
// 2=sigmoid()*X.  BM=64, BN=128, BK=16, 256 threads, 4x8 thread tile with
// f32x2 packed accumulators (2 cols per packed reg).
// ---------------------------------------------------------------------------
template <int ACT>
__global__ __launch_bounds__(256) void gemm_kernel(
    const float* __restrict__ A, const float* __restrict__ B,
    const float* __restrict__ bias, float* __restrict__ C,
    int M, int N, int K, const float* __restrict__ X)
{
    constexpr int BM = 64, BN = 128, BK = 16;
    __shared__ float As[BK][BM];   // transposed A tile
    __shared__ float Bs[BK][BN];

    const int tid = threadIdx.x;
    const int tx  = tid & 15;        // 16 col-groups of 8
    const int ty  = tid >> 4;        // 16 row-groups of 4
    const int m0  = blockIdx.y * BM;
    const int n0  = blockIdx.x * BN;

    const int a_r = tid & 63;        // A tile row
    const int a_c = (tid >> 6) << 2; // A tile k (4 consecutive)
    const int b_r = tid >> 4;        // B tile k row
    const int b_c = (tid & 15) << 3; // B tile col (8 floats)

    unsigned long long acc[4][4];
#pragma unroll
    for (int i = 0; i < 4; i++)
#pragma unroll
        for (int j = 0; j < 4; j++) acc[i][j] = 0ULL;

    for (int k0 = 0; k0 < K; k0 += BK) {
        // load A (scalar; K can be odd, M ragged)
#pragma unroll
        for (int i = 0; i < 4; i++) {
            int k = k0 + a_c + i;
            int m = m0 + a_r;
            As[a_c + i][a_r] = (m < M && k < K) ? A[(size_t)m * K + k] : 0.0f;
        }
        // load B (N is always a multiple of 128 here)
        {
            int kb = k0 + b_r;
            float4 v0 = make_float4(0, 0, 0, 0), v1 = v0;
            if (kb < K) {
                const float4* src =
                    reinterpret_cast<const float4*>(B + (size_t)kb * N + n0 + b_c);
                v0 = src[0];
                v1 = src[1];
            }
            *reinterpret_cast<float4*>(&Bs[b_r][b_c])     = v0;
            *reinterpret_cast<float4*>(&Bs[b_r][b_c + 4]) = v1;
        }
        __syncthreads();

#pragma unroll
        for (int kk = 0; kk < BK; kk++) {
            float4 av = *reinterpret_cast<const float4*>(&As[kk][ty << 2]);
            unsigned long long a2[4];
            a2[0] = pack2(av.x, av.x);
            a2[1] = pack2(av.y, av.y);
            a2[2] = pack2(av.z, av.z);
            a2[3] = pack2(av.w, av.w);
            const unsigned long long* bp =
                reinterpret_cast<const unsigned long long*>(&Bs[kk][tx << 3]);
            unsigned long long b2[4] = {bp[0], bp[1], bp[2], bp[3]};
#pragma unroll
            for (int i = 0; i < 4; i++)
#pragma unroll
                for (int j = 0; j < 4; j++) fma2(acc[i][j], a2[i], b2[j]);
        }
        __syncthreads();
    }

    // epilogue
#pragma unroll
    for (int i = 0; i < 4; i++) {
        int m = m0 + (ty << 2) + i;
        if (m >= M) continue;
        float bv = bias[m];
#pragma unroll
        for (int j = 0; j < 4; j++) {
            float lo, hi;
            unpack2(lo, hi, acc[i][j]);
            int n = n0 + (tx << 3) + 2 * j;
            size_t idx = (size_t)m * N + n;
            float v0 = lo + bv, v1 = hi + bv;
            if (ACT == 0) {
                v0 = (v0 >= 0.0f) ? v0 : 0.01f * v0;
                v1 = (v1 >= 0.0f) ? v1 : 0.01f * v1;
            } else if (ACT == 2) {
                v0 = sigf(v0) * X[idx];
                v1 = sigf(v1) * X[idx + 1];
            }
            C[idx]     = v0;
            C[idx + 1] = v1;
        }
    }
}

// ---------------------------------------------------------------------------
// bias sum: bsum = b_ih + b_hh
// ---------------------------------------------------------------------------
__global__ void bias_sum_kernel(const float* __restrict__ a,
                                const float* __restrict__ b,
                                float* __restrict__ out, int n)
{
    int i = blockIdx.x * blockDim.x + threadIdx.x;
    if (i < n) out[i] = a[i] + b[i];
}

// ---------------------------------------------------------------------------
// LSTM scan: 8-CTA cluster, each CTA owns 100 of the 800 gate rows with its
// W_hh slice in SMEM (fp32, padded pitch 204 for conflict-free LDS.128).
// Per step: each CTA computes its gate slice = Gx[:,t] + Wslice @ h, pushes
// the 100 values into every cluster CTA's SMEM (st.shared::cluster), one
// cluster barrier (arrive=release / wait=acquire), then every CTA redundantly
// runs the full 200-element LSTM update on its local h/c copies (so no h
// broadcast is needed).  Gates are double-buffered on t&1 so step t+1 writes
// never race step t reads.  CTA 0 streams h into Cat rows 0..200.
// ---------------------------------------------------------------------------
__global__ void __cluster_dims__(8, 1, 1) __launch_bounds__(128)
lstm_scan_kernel(const float* __restrict__ Whh, const float* __restrict__ Gx,
                 float* __restrict__ Hout, int F)
{
    constexpr int RPC = 100;   // gate rows per CTA
    constexpr int WP  = 204;   // W pitch (floats), conflict-free for float4

    extern __shared__ float sm[];
    float* Wsh   = sm;                 // RPC * WP
    float* gates = sm + RPC * WP;      // 2 * 800 (double buffered)
    float* hbuf  = gates + 1600;       // 200
    float* cbuf  = hbuf + 200;         // 200

    const int tid  = threadIdx.x;
    const int rank = blockIdx.x;       // == cluster ctarank (single cluster)
    const int row0 = rank * RPC;

    // load W_hh slice into padded SMEM
    for (int idx = tid; idx < RPC * 200; idx += 128) {
        int r = idx / 200;
        int k = idx - r * 200;
        Wsh[r * WP + k] = Whh[(size_t)(row0 + r) * 200 + k];
    }
    for (int j = tid; j < 200; j += 128) { hbuf[j] = 0.0f; cbuf[j] = 0.0f; }
    __syncthreads();

    // per-peer DSMEM addresses of the gates array
    uint32_t gaddr;
    asm("{ .reg .u64 t; cvta.to.shared.u64 t, %1; cvt.u32.u64 %0, t; }"
        : "=r"(gaddr) : "l"(gates));
    uint32_t peer[8];
#pragma unroll
    for (int r = 0; r < 8; r++)
        asm("mapa.shared::cluster.u32 %0, %1, %2;"
            : "=r"(peer[r]) : "r"(gaddr), "r"(r));

    for (int t = 0; t < F; t++) {
        const int buf = t & 1;
        float* gcur = gates + buf * 800;

        if (tid < RPC) {
            const int grow = row0 + tid;
            float gx = __ldg(&Gx[(size_t)grow * F + t]);   // hidden behind FMA loop
            const float4* wr = reinterpret_cast<const float4*>(Wsh + tid * WP);
            const float4* h4 = reinterpret_cast<const float4*>(hbuf);
            float acc = 0.0f;
#pragma unroll
            for (int k = 0; k < 50; k++) {
                float4 w  = wr[k];
                float4 hv = h4[k];
                acc = fmaf(w.x, hv.x, acc);
                acc = fmaf(w.y, hv.y, acc);
                acc = fmaf(w.z, hv.z, acc);
                acc = fmaf(w.w, hv.w, acc);
            }
            float gval = acc + gx;
            uint32_t off = (uint32_t)((buf * 800 + grow) * 4);
#pragma unroll
            for (int r = 0; r < 8; r++)
                asm volatile("st.shared::cluster.f32 [%0], %1;"
                             :: "r"(peer[r] + off), "f"(gval) : "memory");
        }

        // cluster barrier: arrive releases our DSMEM stores, wait acquires peers'
        asm volatile("barrier.cluster.arrive.aligned;" ::: "memory");
        asm volatile("barrier.cluster.wait.aligned;"   ::: "memory");

        // redundant full LSTM update per CTA (keeps h local; no broadcast)
        for (int j = tid; j < 200; j += 128) {
            float gi = gcur[j];
            float gf = gcur[200 + j];
            float gg = gcur[400 + j];
            float go = gcur[600 + j];
            float cn = sigf(gf) * cbuf[j] + sigf(gi) * tanhf(gg);
            float hn = sigf(go) * tanhf(cn);
            cbuf[j] = cn;
            hbuf[j] = hn;
            if (rank == 0) Hout[(size_t)j * F + t] = hn;
        }
        __syncthreads();   // h/c writes visible before next step's compute
    }
}

// ---------------------------------------------------------------------------
// launch
// ---------------------------------------------------------------------------
extern "C" void kernel_launch(void* const* d_in, const int* in_sizes, int n_in,
                              void* d_out, int out_size)
{
    const float* mag = (const float*)d_in[0];
    const float* W1  = (const float*)d_in[1];
    const float* b1  = (const float*)d_in[2];
    const float* W2  = (const float*)d_in[3];
    const float* b2  = (const float*)d_in[4];
    const float* W3  = (const float*)d_in[5];
    const float* b3  = (const float*)d_in[6];
    const float* W4  = (const float*)d_in[7];
    const float* b4  = (const float*)d_in[8];
    const float* Wf1 = (const float*)d_in[9];
    const float* bf1 = (const float*)d_in[10];
    const float* Wf2 = (const float*)d_in[11];
    const float* bf2 = (const float*)d_in[12];
    const float* Wih = (const float*)d_in[13];
    const float* bih = (const float*)d_in[14];
    const float* Whh = (const float*)d_in[15];
    const float* bhh = (const float*)d_in[16];

    const int F = in_sizes[0] / 2049;
    float* out = (float*)d_out;

    float *E1, *Cat, *Gxp, *T1, *T2, *D, *bsum;
    cudaGetSymbolAddress((void**)&E1,   g_E1);
    cudaGetSymbolAddress((void**)&Cat,  g_Cat);
    cudaGetSymbolAddress((void**)&Gxp,  g_Gx);
    cudaGetSymbolAddress((void**)&T1,   g_T1);
    cudaGetSymbolAddress((void**)&T2,   g_T2);
    cudaGetSymbolAddress((void**)&D,    g_D);
    cudaGetSymbolAddress((void**)&bsum, g_bsum);

    float* E = Cat + (size_t)200 * F;   // E lives inside Cat rows 200..600

    const int SCAN_SMEM = (100 * 204 + 1600 + 400) * (int)sizeof(float); // 89.6 KB
    cudaFuncSetAttribute(lstm_scan_kernel,
                         cudaFuncAttributeMaxDynamicSharedMemorySize, SCAN_SMEM);

    dim3 blk(256);
    auto grid = [&](int M) { return dim3(F / 128, (M + 63) / 64); };

    // bsum = b_ih + b_hh
    bias_sum_kernel<<<4, 256>>>(bih, bhh, bsum, 800);

    // phase 1 (batched)
    gemm_kernel<0><<<grid(1000), blk>>>(W1,  mag, b1,   E1,  1000, F, 2049, nullptr);
    gemm_kernel<0><<<grid(400),  blk>>>(W2,  E1,  b2,   E,    400, F, 1000, nullptr);
    gemm_kernel<1><<<grid(800),  blk>>>(Wih, E,   bsum, Gxp,  800, F,  400, nullptr);

    // sequential LSTM scan -> Cat rows 0..200
    lstm_scan_kernel<<<8, 128, SCAN_SMEM>>>(Whh, Gxp, Cat, F);

    // phase 2 (batched)
    gemm_kernel<0><<<grid(800),  blk>>>(Wf1, Cat, bf1, T1,  800, F,  600, nullptr);
    gemm_kernel<0><<<grid(400),  blk>>>(Wf2, T1,  bf2, T2,  400, F,  800, nullptr);
    gemm_kernel<0><<<grid(1000), blk>>>(W3,  T2,  b3,  D,  1000, F,  400, nullptr);
    gemm_kernel<2><<<grid(2049), blk>>>(W4,  D,   b4,  out, 2049, F, 1000, mag);
}